// round 4
// baseline (speedup 1.0000x reference)
#include <cuda_runtime.h>
#include <math.h>
#include <stdint.h>

#define BATCH  2
#define SEQ    2048
#define DMODEL 2048
#define NH     16
#define DHEAD  128
#define MROWS  (BATCH*SEQ)   // 4096

// Scratch (allocation-free rule: __device__ globals)
__device__ float g_q[(size_t)MROWS*DMODEL];     // [b,s,h,e] = [4096,2048]
__device__ float g_k[(size_t)MROWS*DHEAD];      // [b,s,e]
__device__ float g_v[(size_t)MROWS*DHEAD];
__device__ float g_attn[(size_t)MROWS*DMODEL];  // [b,q,h,e]

// ---------------------------------------------------------------------------
// Generic tiled SGEMM: C[M,N] = A[M,K] * B[K,N] (+ bias[N]), all row-major.
// Requires M%BM==0, N%BN==0, K%BK==0 (true for all shapes here).
// ---------------------------------------------------------------------------
template<int BM,int BN,int BK,int TM,int TN,bool BIAS>
__global__ __launch_bounds__((BM/TM)*(BN/TN))
void sgemm_kernel(const float* __restrict__ A, const float* __restrict__ B,
                  const float* __restrict__ bias, float* __restrict__ C,
                  int M, int N, int K)
{
    constexpr int THREADS = (BM/TM)*(BN/TN);
    constexpr int LA = (BM*BK)/(4*THREADS);   // float4 loads of A per thread
    constexpr int LB = (BK*BN)/(4*THREADS);   // float4 loads of B per thread
    static_assert(LA >= 1 && LB >= 1, "tile/thread mismatch");

    __shared__ float As[BK][BM+1];   // transposed, padded (STS conflict relief)
    __shared__ float Bs[BK][BN];

    const int tid = threadIdx.x;
    const int tx  = tid % (BN/TN);
    const int ty  = tid / (BN/TN);
    const int m0  = blockIdx.x * BM;
    const int n0  = blockIdx.y * BN;

    float acc[TM][TN];
    #pragma unroll
    for (int r = 0; r < TM; r++)
        #pragma unroll
        for (int c = 0; c < TN; c++) acc[r][c] = 0.f;

    for (int k0 = 0; k0 < K; k0 += BK) {
        #pragma unroll
        for (int i = 0; i < LA; i++) {
            int idx = tid + i*THREADS;           // float4 index in BM x BK tile
            int row = idx / (BK/4);
            int c4  = idx % (BK/4);
            float4 t = *reinterpret_cast<const float4*>(
                A + (size_t)(m0+row)*K + k0 + c4*4);
            As[c4*4+0][row] = t.x; As[c4*4+1][row] = t.y;
            As[c4*4+2][row] = t.z; As[c4*4+3][row] = t.w;
        }
        #pragma unroll
        for (int i = 0; i < LB; i++) {
            int idx = tid + i*THREADS;           // float4 index in BK x BN tile
            int row = idx / (BN/4);
            int c4  = idx % (BN/4);
            *reinterpret_cast<float4*>(&Bs[row][c4*4]) =
                *reinterpret_cast<const float4*>(
                    B + (size_t)(k0+row)*N + n0 + c4*4);
        }
        __syncthreads();

        #pragma unroll
        for (int kk = 0; kk < BK; kk++) {
            float a[TM];
            #pragma unroll
            for (int r = 0; r < TM; r++) a[r] = As[kk][ty*TM + r];
            float b[TN];
            #pragma unroll
            for (int c = 0; c < TN; c += 4) {
                float4 bv = *reinterpret_cast<const float4*>(&Bs[kk][tx*TN + c]);
                b[c] = bv.x; b[c+1] = bv.y; b[c+2] = bv.z; b[c+3] = bv.w;
            }
            #pragma unroll
            for (int r = 0; r < TM; r++)
                #pragma unroll
                for (int c = 0; c < TN; c++)
                    acc[r][c] = fmaf(a[r], b[c], acc[r][c]);
        }
        __syncthreads();
    }

    #pragma unroll
    for (int r = 0; r < TM; r++) {
        float* crow = C + (size_t)(m0 + ty*TM + r)*N + n0 + tx*TN;
        #pragma unroll
        for (int c = 0; c < TN; c += 4) {
            float4 o;
            o.x = acc[r][c];   o.y = acc[r][c+1];
            o.z = acc[r][c+2]; o.w = acc[r][c+3];
            if (BIAS) {
                const float* bb = bias + n0 + tx*TN + c;
                o.x += bb[0]; o.y += bb[1]; o.z += bb[2]; o.w += bb[3];
            }
            *reinterpret_cast<float4*>(crow + c) = o;
        }
    }
}

// ---------------------------------------------------------------------------
// Flash attention (causal, MQA: shared K/V across heads), fp32.
// Block: 64 queries x one (b,h). Threads: 256 as 16x16.
// Smem: Qt[128][65], Kt[128][65] (transposed, padded), Vs[64][128], Ps[64][65].
// ---------------------------------------------------------------------------
#define FA_SMEM_FLOATS (128*65 + 128*65 + 64*128 + 64*65)

__global__ __launch_bounds__(256)
void flash_kernel(const float* __restrict__ q, const float* __restrict__ k,
                  const float* __restrict__ v, float* __restrict__ outp)
{
    extern __shared__ float sm[];
    float* Qt = sm;               // [e][i]  128 x 65
    float* Kt = Qt + 128*65;      // [e][j]  128 x 65
    float* Vs = Kt + 128*65;      // [j][d]  64 x 128
    float* Ps = Vs + 64*128;      // [i][j]  64 x 65

    const int q0 = blockIdx.x * 64;
    const int h  = blockIdx.y;
    const int b  = blockIdx.z;
    const int tid = threadIdx.x;
    const int tx = tid & 15;
    const int ty = tid >> 4;
    const int i0 = ty * 4;     // S-tile rows owned (4)
    const int j0 = tx * 4;     // S-tile cols owned (4)
    const int d0 = tx * 8;     // O cols owned (8)

    // --- load Q tile transposed ---
    const float* qb = q + ((size_t)((size_t)b*SEQ + q0)*NH + h)*DHEAD;
    #pragma unroll
    for (int it = 0; it < 8; it++) {
        int idx = tid + it*256;          // 2048 float4s
        int row = idx >> 5, c4 = idx & 31;
        float4 t = *reinterpret_cast<const float4*>(
            qb + (size_t)row*(NH*DHEAD) + c4*4);
        Qt[(c4*4+0)*65+row] = t.x; Qt[(c4*4+1)*65+row] = t.y;
        Qt[(c4*4+2)*65+row] = t.z; Qt[(c4*4+3)*65+row] = t.w;
    }

    float m_i[4], l_i[4], acc[4][8];
    #pragma unroll
    for (int r = 0; r < 4; r++) {
        m_i[r] = -INFINITY; l_i[r] = 0.f;
        #pragma unroll
        for (int c = 0; c < 8; c++) acc[r][c] = 0.f;
    }

    const int ntiles = (q0 >> 6) + 1;
    const float scale = 0.08838834764831845f;  // 1/sqrt(128)

    for (int jt = 0; jt < ntiles; jt++) {
        const int kv0 = jt * 64;
        __syncthreads();   // protect Kt/Vs/Ps reuse + Qt visibility on first iter

        const float* kb = k + ((size_t)b*SEQ + kv0)*DHEAD;
        const float* vb = v + ((size_t)b*SEQ + kv0)*DHEAD;
        #pragma unroll
        for (int it = 0; it < 8; it++) {
            int idx = tid + it*256;
            int row = idx >> 5, c4 = idx & 31;
            float4 t = *reinterpret_cast<const float4*>(kb + (size_t)row*DHEAD + c4*4);
            Kt[(c4*4+0)*65+row] = t.x; Kt[(c4*4+1)*65+row] = t.y;
            Kt[(c4*4+2)*65+row] = t.z; Kt[(c4*4+3)*65+row] = t.w;
            float4 tv = *reinterpret_cast<const float4*>(vb + (size_t)row*DHEAD + c4*4);
            *reinterpret_cast<float4*>(Vs + row*128 + c4*4) = tv;
        }
        __syncthreads();

        // --- S = Q K^T (4x4 per thread) ---
        float s[4][4];
        #pragma unroll
        for (int r = 0; r < 4; r++)
            #pragma unroll
            for (int c = 0; c < 4; c++) s[r][c] = 0.f;

        #pragma unroll 4
        for (int e = 0; e < 128; e++) {
            const float* qr = Qt + e*65;
            const float* kr = Kt + e*65;
            float a0 = qr[i0+0], a1 = qr[i0+1], a2 = qr[i0+2], a3 = qr[i0+3];
            float b0 = kr[j0+0], b1 = kr[j0+1], b2 = kr[j0+2], b3 = kr[j0+3];
            s[0][0]=fmaf(a0,b0,s[0][0]); s[0][1]=fmaf(a0,b1,s[0][1]);
            s[0][2]=fmaf(a0,b2,s[0][2]); s[0][3]=fmaf(a0,b3,s[0][3]);
            s[1][0]=fmaf(a1,b0,s[1][0]); s[1][1]=fmaf(a1,b1,s[1][1]);
            s[1][2]=fmaf(a1,b2,s[1][2]); s[1][3]=fmaf(a1,b3,s[1][3]);
            s[2][0]=fmaf(a2,b0,s[2][0]); s[2][1]=fmaf(a2,b1,s[2][1]);
            s[2][2]=fmaf(a2,b2,s[2][2]); s[2][3]=fmaf(a2,b3,s[2][3]);
            s[3][0]=fmaf(a3,b0,s[3][0]); s[3][1]=fmaf(a3,b1,s[3][1]);
            s[3][2]=fmaf(a3,b2,s[3][2]); s[3][3]=fmaf(a3,b3,s[3][3]);
        }

        // --- scale + causal mask (diagonal tile only) ---
        const bool diag = (jt == ntiles - 1);
        #pragma unroll
        for (int r = 0; r < 4; r++)
            #pragma unroll
            for (int c = 0; c < 4; c++) {
                float sv = s[r][c] * scale;
                if (diag && (kv0 + j0 + c) > (q0 + i0 + r)) sv = -INFINITY;
                s[r][c] = sv;
            }

        // --- online softmax (row reduce over 16 tx lanes) ---
        #pragma unroll
        for (int r = 0; r < 4; r++) {
            float rm = fmaxf(fmaxf(s[r][0], s[r][1]), fmaxf(s[r][2], s[r][3]));
            #pragma unroll
            for (int off = 8; off >= 1; off >>= 1)
                rm = fmaxf(rm, __shfl_xor_sync(0xffffffffu, rm, off));
            float mnew = fmaxf(m_i[r], rm);
            float corr = __expf(m_i[r] - mnew);
            float rs = 0.f;
            #pragma unroll
            for (int c = 0; c < 4; c++) {
                float p = __expf(s[r][c] - mnew);
                Ps[(i0 + r)*65 + j0 + c] = p;
                rs += p;
            }
            #pragma unroll
            for (int off = 8; off >= 1; off >>= 1)
                rs += __shfl_xor_sync(0xffffffffu, rs, off);
            l_i[r] = l_i[r] * corr + rs;
            m_i[r] = mnew;
            #pragma unroll
            for (int c = 0; c < 8; c++) acc[r][c] *= corr;
        }
        __syncthreads();

        // --- O += P V ---
        #pragma unroll 4
        for (int j = 0; j < 64; j++) {
            float pr[4];
            pr[0] = Ps[(i0+0)*65 + j]; pr[1] = Ps[(i0+1)*65 + j];
            pr[2] = Ps[(i0+2)*65 + j]; pr[3] = Ps[(i0+3)*65 + j];
            float4 v0 = *reinterpret_cast<const float4*>(Vs + j*128 + d0);
            float4 v1 = *reinterpret_cast<const float4*>(Vs + j*128 + d0 + 4);
            float vv[8] = {v0.x, v0.y, v0.z, v0.w, v1.x, v1.y, v1.z, v1.w};
            #pragma unroll
            for (int r = 0; r < 4; r++)
                #pragma unroll
                for (int c = 0; c < 8; c++)
                    acc[r][c] = fmaf(pr[r], vv[c], acc[r][c]);
        }
    }

    // --- epilogue: normalize and store attn [b,q,h,e] ---
    float* ob = outp + ((size_t)((size_t)b*SEQ + q0)*NH + h)*DHEAD;
    #pragma unroll
    for (int r = 0; r < 4; r++) {
        float inv = 1.0f / l_i[r];
        float4 o0, o1;
        o0.x = acc[r][0]*inv; o0.y = acc[r][1]*inv;
        o0.z = acc[r][2]*inv; o0.w = acc[r][3]*inv;
        o1.x = acc[r][4]*inv; o1.y = acc[r][5]*inv;
        o1.z = acc[r][6]*inv; o1.w = acc[r][7]*inv;
        float* row = ob + (size_t)(i0 + r)*(NH*DHEAD) + d0;
        *reinterpret_cast<float4*>(row)     = o0;
        *reinterpret_cast<float4*>(row + 4) = o1;
    }
}

// ---------------------------------------------------------------------------
// Launch: x(0), mask(1, ignored: mask is tril/causal by construction),
//         Wq(2) [D,H,DH], Wk(3) [D,1,DH], Wv(4), Wo(5) [H,DH,D], bo(6) [D]
// out: float32 [B,S,D]
// ---------------------------------------------------------------------------
extern "C" void kernel_launch(void* const* d_in, const int* in_sizes, int n_in,
                              void* d_out, int out_size)
{
    const float* x  = (const float*)d_in[0];
    const float* Wq = (const float*)d_in[2];
    const float* Wk = (const float*)d_in[3];
    const float* Wv = (const float*)d_in[4];
    const float* Wo = (const float*)d_in[5];
    const float* bo = (const float*)d_in[6];
    float* out = (float*)d_out;

    float *dq, *dk, *dv, *da;
    cudaGetSymbolAddress((void**)&dq, g_q);
    cudaGetSymbolAddress((void**)&dk, g_k);
    cudaGetSymbolAddress((void**)&dv, g_v);
    cudaGetSymbolAddress((void**)&da, g_attn);

    // Q projection: [4096,2048] x [2048,2048] -> g_q [b,s,h,e]
    sgemm_kernel<128,128,16,8,8,false>
        <<<dim3(MROWS/128, DMODEL/128), 256>>>(x, Wq, nullptr, dq,
                                               MROWS, DMODEL, DMODEL);
    // K,V projections: [4096,2048] x [2048,128]
    sgemm_kernel<64,128,16,4,8,false>
        <<<dim3(MROWS/64, 1), 256>>>(x, Wk, nullptr, dk, MROWS, DHEAD, DMODEL);
    sgemm_kernel<64,128,16,4,8,false>
        <<<dim3(MROWS/64, 1), 256>>>(x, Wv, nullptr, dv, MROWS, DHEAD, DMODEL);

    // Flash attention
    const int smem = FA_SMEM_FLOATS * (int)sizeof(float);   // 115,968 B
    cudaFuncSetAttribute(flash_kernel,
                         cudaFuncAttributeMaxDynamicSharedMemorySize, smem);
    flash_kernel<<<dim3(SEQ/64, NH, BATCH), 256, smem>>>(dq, dk, dv, da);

    // Output projection + bias: [4096,2048] x [2048,2048] -> out
    sgemm_kernel<128,128,16,8,8,true>
        <<<dim3(MROWS/128, DMODEL/128), 256>>>(da, Wo, bo, out,
                                               MROWS, DMODEL, DMODEL);
}

// round 7
// speedup vs baseline: 1.3007x; 1.3007x over previous
#include <cuda_runtime.h>
#include <cuda_bf16.h>
#include <math.h>
#include <stdint.h>

#define BATCH  2
#define SEQ    2048
#define DMODEL 2048
#define NH     16
#define DHEAD  128
#define MROWS  (BATCH*SEQ)   // 4096

// ---------------------------------------------------------------------------
// Scratch (allocation-free rule: __device__ globals)
// ---------------------------------------------------------------------------
__device__ float g_q   [(size_t)MROWS*DMODEL];   // Q proj out [b,s,h,e]
__device__ float g_k   [(size_t)MROWS*DHEAD];
__device__ float g_v   [(size_t)MROWS*DHEAD];
__device__ float g_attn[(size_t)MROWS*DMODEL];   // attention out [b,q,h,e]

__device__ __nv_bfloat16 g_xhi[(size_t)MROWS*DMODEL];
__device__ __nv_bfloat16 g_xlo[(size_t)MROWS*DMODEL];
__device__ __nv_bfloat16 g_ahi[(size_t)MROWS*DMODEL];
__device__ __nv_bfloat16 g_alo[(size_t)MROWS*DMODEL];
__device__ __nv_bfloat16 g_wqh[(size_t)DMODEL*DMODEL];  // Wq^T [n][k]
__device__ __nv_bfloat16 g_wql[(size_t)DMODEL*DMODEL];
__device__ __nv_bfloat16 g_woh[(size_t)DMODEL*DMODEL];  // Wo^T [n][k]
__device__ __nv_bfloat16 g_wol[(size_t)DMODEL*DMODEL];

// ---------------------------------------------------------------------------
// PTX helpers (baseline features only: sm_80-level, safe on compute_103)
// ---------------------------------------------------------------------------
__device__ __forceinline__ uint32_t smem_u32(const void* p) {
    uint32_t a;
    asm("{ .reg .u64 t; cvta.to.shared.u64 t, %1; cvt.u32.u64 %0, t; }"
        : "=r"(a) : "l"(p));
    return a;
}
__device__ __forceinline__ void cp16(uint32_t s, const void* g) {
    asm volatile("cp.async.cg.shared.global [%0], [%1], 16;" :: "r"(s), "l"(g));
}
__device__ __forceinline__ void cp_commit() {
    asm volatile("cp.async.commit_group;" ::: "memory");
}
template<int N> __device__ __forceinline__ void cp_wait() {
    asm volatile("cp.async.wait_group %0;" :: "n"(N) : "memory");
}
__device__ __forceinline__ void ldsm4(uint32_t& r0, uint32_t& r1,
                                      uint32_t& r2, uint32_t& r3, uint32_t addr) {
    asm volatile("ldmatrix.sync.aligned.m8n8.x4.shared.b16 {%0,%1,%2,%3}, [%4];"
                 : "=r"(r0), "=r"(r1), "=r"(r2), "=r"(r3) : "r"(addr));
}
__device__ __forceinline__ void mma_bf16(float* c, const uint32_t* a,
                                         const uint32_t* b) {
    asm volatile(
        "mma.sync.aligned.m16n8k16.row.col.f32.bf16.bf16.f32 "
        "{%0,%1,%2,%3}, {%4,%5,%6,%7}, {%8,%9}, {%0,%1,%2,%3};"
        : "+f"(c[0]), "+f"(c[1]), "+f"(c[2]), "+f"(c[3])
        : "r"(a[0]), "r"(a[1]), "r"(a[2]), "r"(a[3]), "r"(b[0]), "r"(b[1]));
}

// ---------------------------------------------------------------------------
// bf16-split tensor-core GEMM:
//   C[M=4096, N=2048] = A[M,K=2048] * B^T  with  A ~ Ahi+Alo, B ~ Bhi+Blo,
//   3 passes: AhiBhi + AloBhi + AhiBlo  (fp32 accumulate).
//   A arrays [M,K] K-major bf16; B arrays [N,K] K-major bf16 (pre-transposed).
// CTA tile 128x128, BK=32, 8 warps (warp tile 32x64), 3-stage cp.async.
// ---------------------------------------------------------------------------
#define GB_STRIDE 40                           // bf16 per smem row (32 + 8 pad)
#define GB_TILE_B (128*GB_STRIDE*2)            // 10240 B per operand tile
#define GB_STAGE  (4*GB_TILE_B)                // Ahi,Alo,Bhi,Blo = 40960 B
#define GB_SMEM   (3*GB_STAGE)                 // 122880 B
#define GB_KTILES (DMODEL/32)                  // 64

__device__ __forceinline__ void gb_fill(uint32_t st,
        const __nv_bfloat16* __restrict__ Ah, const __nv_bfloat16* __restrict__ Al,
        const __nv_bfloat16* __restrict__ Bh, const __nv_bfloat16* __restrict__ Bl,
        int m0, int n0, int k0, int tid)
{
    #pragma unroll
    for (int it = 0; it < 2; it++) {
        int c   = tid + it*256;        // 512 chunks of 16B per operand
        int row = c >> 2, cc = c & 3;
        uint32_t off = (uint32_t)row*(GB_STRIDE*2) + cc*16;
        size_t ga = (size_t)(m0+row)*DMODEL + k0 + cc*8;
        size_t gb = (size_t)(n0+row)*DMODEL + k0 + cc*8;
        cp16(st + 0*GB_TILE_B + off, Ah + ga);
        cp16(st + 1*GB_TILE_B + off, Al + ga);
        cp16(st + 2*GB_TILE_B + off, Bh + gb);
        cp16(st + 3*GB_TILE_B + off, Bl + gb);
    }
}

template<bool BIAS>
__global__ __launch_bounds__(256)
void gemm_bf16s_kernel(const __nv_bfloat16* __restrict__ Ah,
                       const __nv_bfloat16* __restrict__ Al,
                       const __nv_bfloat16* __restrict__ Bh,
                       const __nv_bfloat16* __restrict__ Bl,
                       const float* __restrict__ bias, float* __restrict__ C)
{
    extern __shared__ char gsm[];
    const uint32_t sbase = smem_u32(gsm);
    const int tid  = threadIdx.x;
    const int lane = tid & 31;
    const int wid  = tid >> 5;
    const int wm   = wid & 3;          // 4 warps along M
    const int wn   = wid >> 2;         // 2 warps along N
    const int m0   = blockIdx.x * 128;
    const int n0   = blockIdx.y * 128;

    float acc[2][8][4];
    #pragma unroll
    for (int i = 0; i < 2; i++)
        #pragma unroll
        for (int j = 0; j < 8; j++)
            #pragma unroll
            for (int q = 0; q < 4; q++) acc[i][j][q] = 0.f;

    // ldmatrix per-lane address components
    const int a_row = lane & 15;
    const int a_k8  = (lane >> 4) << 3;
    const int bmat  = lane >> 3;
    const int b_row = ((bmat & 2) << 2) + (lane & 7);   // +8 for matrices 2,3
    const int b_k8  = (bmat & 1) << 3;

    // prologue
    gb_fill(sbase + 0*GB_STAGE, Ah, Al, Bh, Bl, m0, n0, 0,  tid); cp_commit();
    gb_fill(sbase + 1*GB_STAGE, Ah, Al, Bh, Bl, m0, n0, 32, tid); cp_commit();

    for (int t = 0; t < GB_KTILES; t++) {
        if (t < GB_KTILES-1) cp_wait<1>(); else cp_wait<0>();
        __syncthreads();

        if (t + 2 < GB_KTILES) {
            gb_fill(sbase + ((t+2)%3)*GB_STAGE, Ah, Al, Bh, Bl,
                    m0, n0, (t+2)*32, tid);
            cp_commit();
        }

        const uint32_t st  = sbase + (t%3)*GB_STAGE;
        const uint32_t sAh = st;
        const uint32_t sAl = st + 1*GB_TILE_B;
        const uint32_t sBh = st + 2*GB_TILE_B;
        const uint32_t sBl = st + 3*GB_TILE_B;

        #pragma unroll
        for (int kk = 0; kk < 2; kk++) {
            const int kc = kk*16;
            uint32_t ahi[2][4], alo[2][4], bhi[8][2], blo[8][2];
            #pragma unroll
            for (int mf = 0; mf < 2; mf++) {
                uint32_t off = (uint32_t)(wm*32 + mf*16 + a_row)*(GB_STRIDE*2)
                             + (kc + a_k8)*2;
                ldsm4(ahi[mf][0], ahi[mf][1], ahi[mf][2], ahi[mf][3], sAh + off);
                ldsm4(alo[mf][0], alo[mf][1], alo[mf][2], alo[mf][3], sAl + off);
            }
            #pragma unroll
            for (int p = 0; p < 4; p++) {
                uint32_t off = (uint32_t)(wn*64 + p*16 + b_row)*(GB_STRIDE*2)
                             + (kc + b_k8)*2;
                ldsm4(bhi[2*p][0], bhi[2*p][1], bhi[2*p+1][0], bhi[2*p+1][1],
                      sBh + off);
                ldsm4(blo[2*p][0], blo[2*p][1], blo[2*p+1][0], blo[2*p+1][1],
                      sBl + off);
            }
            #pragma unroll
            for (int mf = 0; mf < 2; mf++)
                #pragma unroll
                for (int nf = 0; nf < 8; nf++) {
                    mma_bf16(acc[mf][nf], ahi[mf], bhi[nf]);
                    mma_bf16(acc[mf][nf], alo[mf], bhi[nf]);
                    mma_bf16(acc[mf][nf], ahi[mf], blo[nf]);
                }
        }
    }

    // epilogue: fragment layout c0,c1 -> (r, 2c),(r,2c+1); c2,c3 -> r+8
    #pragma unroll
    for (int mf = 0; mf < 2; mf++) {
        const int r0 = m0 + wm*32 + mf*16 + (lane >> 2);
        #pragma unroll
        for (int nf = 0; nf < 8; nf++) {
            const int col = n0 + wn*64 + nf*8 + (lane & 3)*2;
            float2 v0 = make_float2(acc[mf][nf][0], acc[mf][nf][1]);
            float2 v1 = make_float2(acc[mf][nf][2], acc[mf][nf][3]);
            if (BIAS) {
                float2 bb = *reinterpret_cast<const float2*>(bias + col);
                v0.x += bb.x; v0.y += bb.y;
                v1.x += bb.x; v1.y += bb.y;
            }
            *reinterpret_cast<float2*>(C + (size_t)r0*DMODEL + col)     = v0;
            *reinterpret_cast<float2*>(C + (size_t)(r0+8)*DMODEL + col) = v1;
        }
    }
}

// ---------------------------------------------------------------------------
// Staging: fp32 -> bf16 hi/lo split; fused transpose+split for weights.
// ---------------------------------------------------------------------------
__global__ __launch_bounds__(256)
void split_kernel(const float* __restrict__ x, __nv_bfloat16* __restrict__ hi,
                  __nv_bfloat16* __restrict__ lo)
{
    int i = blockIdx.x * blockDim.x + threadIdx.x;
    float4 v = reinterpret_cast<const float4*>(x)[i];
    __nv_bfloat16 h0 = __float2bfloat16_rn(v.x);
    __nv_bfloat16 h1 = __float2bfloat16_rn(v.y);
    __nv_bfloat16 h2 = __float2bfloat16_rn(v.z);
    __nv_bfloat16 h3 = __float2bfloat16_rn(v.w);
    __nv_bfloat16 l0 = __float2bfloat16_rn(v.x - __bfloat162float(h0));
    __nv_bfloat16 l1 = __float2bfloat16_rn(v.y - __bfloat162float(h1));
    __nv_bfloat16 l2 = __float2bfloat16_rn(v.z - __bfloat162float(h2));
    __nv_bfloat16 l3 = __float2bfloat16_rn(v.w - __bfloat162float(h3));
    __nv_bfloat162* H = reinterpret_cast<__nv_bfloat162*>(hi);
    __nv_bfloat162* L = reinterpret_cast<__nv_bfloat162*>(lo);
    H[2*i]   = __nv_bfloat162(h0, h1);
    H[2*i+1] = __nv_bfloat162(h2, h3);
    L[2*i]   = __nv_bfloat162(l0, l1);
    L[2*i+1] = __nv_bfloat162(l2, l3);
}

__global__ __launch_bounds__(256)
void transpose_split_kernel(const float* __restrict__ W,
                            __nv_bfloat16* __restrict__ Thi,
                            __nv_bfloat16* __restrict__ Tlo)
{
    __shared__ float tile[32][33];
    const int x0 = blockIdx.x * 32;   // input col / output row
    const int y0 = blockIdx.y * 32;   // input row / output col
    const int tx = threadIdx.x & 31;
    const int ty = threadIdx.x >> 5;  // 0..7
    #pragma unroll
    for (int j = ty; j < 32; j += 8)
        tile[j][tx] = W[(size_t)(y0 + j)*DMODEL + x0 + tx];
    __syncthreads();
    #pragma unroll
    for (int a = ty; a < 32; a += 8) {
        float v = tile[tx][a];
        __nv_bfloat16 h = __float2bfloat16_rn(v);
        __nv_bfloat16 l = __float2bfloat16_rn(v - __bfloat162float(h));
        Thi[(size_t)(x0 + a)*DMODEL + y0 + tx] = h;
        Tlo[(size_t)(x0 + a)*DMODEL + y0 + tx] = l;
    }
}

// ---------------------------------------------------------------------------
// fp32 SGEMM (skinny K/V projections)
// ---------------------------------------------------------------------------
template<int BM,int BN,int BK,int TM,int TN>
__global__ __launch_bounds__((BM/TM)*(BN/TN))
void sgemm_kernel(const float* __restrict__ A, const float* __restrict__ B,
                  float* __restrict__ C, int M, int N, int K)
{
    constexpr int THREADS = (BM/TM)*(BN/TN);
    constexpr int LA = (BM*BK)/(4*THREADS);
    constexpr int LB = (BK*BN)/(4*THREADS);

    __shared__ float As[BK][BM+1];
    __shared__ float Bs[BK][BN];

    const int tid = threadIdx.x;
    const int tx  = tid % (BN/TN);
    const int ty  = tid / (BN/TN);
    const int m0  = blockIdx.x * BM;
    const int n0  = blockIdx.y * BN;

    float acc[TM][TN];
    #pragma unroll
    for (int r = 0; r < TM; r++)
        #pragma unroll
        for (int c = 0; c < TN; c++) acc[r][c] = 0.f;

    for (int k0 = 0; k0 < K; k0 += BK) {
        #pragma unroll
        for (int i = 0; i < LA; i++) {
            int idx = tid + i*THREADS;
            int row = idx / (BK/4);
            int c4  = idx % (BK/4);
            float4 t = *reinterpret_cast<const float4*>(
                A + (size_t)(m0+row)*K + k0 + c4*4);
            As[c4*4+0][row] = t.x; As[c4*4+1][row] = t.y;
            As[c4*4+2][row] = t.z; As[c4*4+3][row] = t.w;
        }
        #pragma unroll
        for (int i = 0; i < LB; i++) {
            int idx = tid + i*THREADS;
            int row = idx / (BN/4);
            int c4  = idx % (BN/4);
            *reinterpret_cast<float4*>(&Bs[row][c4*4]) =
                *reinterpret_cast<const float4*>(
                    B + (size_t)(k0+row)*N + n0 + c4*4);
        }
        __syncthreads();

        #pragma unroll
        for (int kk = 0; kk < BK; kk++) {
            float a[TM];
            #pragma unroll
            for (int r = 0; r < TM; r++) a[r] = As[kk][ty*TM + r];
            float b[TN];
            #pragma unroll
            for (int c = 0; c < TN; c += 4) {
                float4 bv = *reinterpret_cast<const float4*>(&Bs[kk][tx*TN + c]);
                b[c] = bv.x; b[c+1] = bv.y; b[c+2] = bv.z; b[c+3] = bv.w;
            }
            #pragma unroll
            for (int r = 0; r < TM; r++)
                #pragma unroll
                for (int c = 0; c < TN; c++)
                    acc[r][c] = fmaf(a[r], b[c], acc[r][c]);
        }
        __syncthreads();
    }

    #pragma unroll
    for (int r = 0; r < TM; r++) {
        float* crow = C + (size_t)(m0 + ty*TM + r)*N + n0 + tx*TN;
        #pragma unroll
        for (int c = 0; c < TN; c += 4) {
            float4 o;
            o.x = acc[r][c];   o.y = acc[r][c+1];
            o.z = acc[r][c+2]; o.w = acc[r][c+3];
            *reinterpret_cast<float4*>(crow + c) = o;
        }
    }
}

// ---------------------------------------------------------------------------
// Flash attention (causal, MQA), fp32 — unchanged (passing, rel_err 1.7e-6)
// ---------------------------------------------------------------------------
#define FA_SMEM_FLOATS (128*65 + 128*65 + 64*128 + 64*65)

__global__ __launch_bounds__(256)
void flash_kernel(const float* __restrict__ q, const float* __restrict__ k,
                  const float* __restrict__ v, float* __restrict__ outp)
{
    extern __shared__ float sm[];
    float* Qt = sm;               // [e][i]  128 x 65
    float* Kt = Qt + 128*65;      // [e][j]  128 x 65
    float* Vs = Kt + 128*65;      // [j][d]  64 x 128
    float* Ps = Vs + 64*128;      // [i][j]  64 x 65

    const int q0 = blockIdx.x * 64;
    const int h  = blockIdx.y;
    const int b  = blockIdx.z;
    const int tid = threadIdx.x;
    const int tx = tid & 15;
    const int ty = tid >> 4;
    const int i0 = ty * 4;
    const int j0 = tx * 4;
    const int d0 = tx * 8;

    const float* qb = q + ((size_t)((size_t)b*SEQ + q0)*NH + h)*DHEAD;
    #pragma unroll
    for (int it = 0; it < 8; it++) {
        int idx = tid + it*256;
        int row = idx >> 5, c4 = idx & 31;
        float4 t = *reinterpret_cast<const float4*>(
            qb + (size_t)row*(NH*DHEAD) + c4*4);
        Qt[(c4*4+0)*65+row] = t.x; Qt[(c4*4+1)*65+row] = t.y;
        Qt[(c4*4+2)*65+row] = t.z; Qt[(c4*4+3)*65+row] = t.w;
    }

    float m_i[4], l_i[4], acc[4][8];
    #pragma unroll
    for (int r = 0; r < 4; r++) {
        m_i[r] = -INFINITY; l_i[r] = 0.f;
        #pragma unroll
        for (int c = 0; c < 8; c++) acc[r][c] = 0.f;
    }

    const int ntiles = (q0 >> 6) + 1;
    const float scale = 0.08838834764831845f;

    for (int jt = 0; jt < ntiles; jt++) {
        const int kv0 = jt * 64;
        __syncthreads();

        const float* kb = k + ((size_t)b*SEQ + kv0)*DHEAD;
        const float* vb = v + ((size_t)b*SEQ + kv0)*DHEAD;
        #pragma unroll
        for (int it = 0; it < 8; it++) {
            int idx = tid + it*256;
            int row = idx >> 5, c4 = idx & 31;
            float4 t = *reinterpret_cast<const float4*>(kb + (size_t)row*DHEAD + c4*4);
            Kt[(c4*4+0)*65+row] = t.x; Kt[(c4*4+1)*65+row] = t.y;
            Kt[(c4*4+2)*65+row] = t.z; Kt[(c4*4+3)*65+row] = t.w;
            float4 tv = *reinterpret_cast<const float4*>(vb + (size_t)row*DHEAD + c4*4);
            *reinterpret_cast<float4*>(Vs + row*128 + c4*4) = tv;
        }
        __syncthreads();

        float s[4][4];
        #pragma unroll
        for (int r = 0; r < 4; r++)
            #pragma unroll
            for (int c = 0; c < 4; c++) s[r][c] = 0.f;

        #pragma unroll 4
        for (int e = 0; e < 128; e++) {
            const float* qr = Qt + e*65;
            const float* kr = Kt + e*65;
            float a0 = qr[i0+0], a1 = qr[i0+1], a2 = qr[i0+2], a3 = qr[i0+3];
            float b0 = kr[j0+0], b1 = kr[j0+1], b2 = kr[j0+2], b3 = kr[j0+3];
            s[0][0]=fmaf(a0,b0,s[0][0]); s[0][1]=fmaf(a0,b1,s[0][1]);
            s[0][2]=fmaf(a0,b2,s[0][2]); s[0][3]=fmaf(a0,b3,s[0][3]);
            s[1][0]=fmaf(a1,b0,s[1][0]); s[1][1]=fmaf(a1,b1,s[1][1]);
            s[1][2]=fmaf(a1,b2,s[1][2]); s[1][3]=fmaf(a1,b3,s[1][3]);
            s[2][0]=fmaf(a2,b0,s[2][0]); s[2][1]=fmaf(a2,b1,s[2][1]);
            s[2][2]=fmaf(a2,b2,s[2][2]); s[2][3]=fmaf(a2,b3,s[2][3]);
            s[3][0]=fmaf(a3,b0,s[3][0]); s[3][1]=fmaf(a3,b1,s[3][1]);
            s[3][2]=fmaf(a3,b2,s[3][2]); s[3][3]=fmaf(a3,b3,s[3][3]);
        }

        const bool diag = (jt == ntiles - 1);
        #pragma unroll
        for (int r = 0; r < 4; r++)
            #pragma unroll
            for (int c = 0; c < 4; c++) {
                float sv = s[r][c] * scale;
                if (diag && (kv0 + j0 + c) > (q0 + i0 + r)) sv = -INFINITY;
                s[r][c] = sv;
            }

        #pragma unroll
        for (int r = 0; r < 4; r++) {
            float rm = fmaxf(fmaxf(s[r][0], s[r][1]), fmaxf(s[r][2], s[r][3]));
            #pragma unroll
            for (int off = 8; off >= 1; off >>= 1)
                rm = fmaxf(rm, __shfl_xor_sync(0xffffffffu, rm, off));
            float mnew = fmaxf(m_i[r], rm);
            float corr = __expf(m_i[r] - mnew);
            float rs = 0.f;
            #pragma unroll
            for (int c = 0; c < 4; c++) {
                float p = __expf(s[r][c] - mnew);
                Ps[(i0 + r)*65 + j0 + c] = p;
                rs += p;
            }
            #pragma unroll
            for (int off = 8; off >= 1; off >>= 1)
                rs += __shfl_xor_sync(0xffffffffu, rs, off);
            l_i[r] = l_i[r] * corr + rs;
            m_i[r] = mnew;
            #pragma unroll
            for (int c = 0; c < 8; c++) acc[r][c] *= corr;
        }
        __syncthreads();

        #pragma unroll 4
        for (int j = 0; j < 64; j++) {
            float pr[4];
            pr[0] = Ps[(i0+0)*65 + j]; pr[1] = Ps[(i0+1)*65 + j];
            pr[2] = Ps[(i0+2)*65 + j]; pr[3] = Ps[(i0+3)*65 + j];
            float4 v0 = *reinterpret_cast<const float4*>(Vs + j*128 + d0);
            float4 v1 = *reinterpret_cast<const float4*>(Vs + j*128 + d0 + 4);
            float vv[8] = {v0.x, v0.y, v0.z, v0.w, v1.x, v1.y, v1.z, v1.w};
            #pragma unroll
            for (int r = 0; r < 4; r++)
                #pragma unroll
                for (int c = 0; c < 8; c++)
                    acc[r][c] = fmaf(pr[r], vv[c], acc[r][c]);
        }
    }

    float* ob = outp + ((size_t)((size_t)b*SEQ + q0)*NH + h)*DHEAD;
    #pragma unroll
    for (int r = 0; r < 4; r++) {
        float inv = 1.0f / l_i[r];
        float4 o0, o1;
        o0.x = acc[r][0]*inv; o0.y = acc[r][1]*inv;
        o0.z = acc[r][2]*inv; o0.w = acc[r][3]*inv;
        o1.x = acc[r][4]*inv; o1.y = acc[r][5]*inv;
        o1.z = acc[r][6]*inv; o1.w = acc[r][7]*inv;
        float* row = ob + (size_t)(i0 + r)*(NH*DHEAD) + d0;
        *reinterpret_cast<float4*>(row)     = o0;
        *reinterpret_cast<float4*>(row + 4) = o1;
    }
}

// ---------------------------------------------------------------------------
// Launch: x(0), mask(1, causal by construction), Wq(2), Wk(3), Wv(4),
//         Wo(5), bo(6).  out: float32 [B,S,D]
// ---------------------------------------------------------------------------
extern "C" void kernel_launch(void* const* d_in, const int* in_sizes, int n_in,
                              void* d_out, int out_size)
{
    const float* x  = (const float*)d_in[0];
    const float* Wq = (const float*)d_in[2];
    const float* Wk = (const float*)d_in[3];
    const float* Wv = (const float*)d_in[4];
    const float* Wo = (const float*)d_in[5];
    const float* bo = (const float*)d_in[6];
    float* out = (float*)d_out;

    float *dq, *dk, *dv, *da;
    __nv_bfloat16 *xhi, *xlo, *ahi, *alo, *wqh, *wql, *woh, *wol;
    cudaGetSymbolAddress((void**)&dq,  g_q);
    cudaGetSymbolAddress((void**)&dk,  g_k);
    cudaGetSymbolAddress((void**)&dv,  g_v);
    cudaGetSymbolAddress((void**)&da,  g_attn);
    cudaGetSymbolAddress((void**)&xhi, g_xhi);
    cudaGetSymbolAddress((void**)&xlo, g_xlo);
    cudaGetSymbolAddress((void**)&ahi, g_ahi);
    cudaGetSymbolAddress((void**)&alo, g_alo);
    cudaGetSymbolAddress((void**)&wqh, g_wqh);
    cudaGetSymbolAddress((void**)&wql, g_wql);
    cudaGetSymbolAddress((void**)&woh, g_woh);
    cudaGetSymbolAddress((void**)&wol, g_wol);

    cudaFuncSetAttribute(gemm_bf16s_kernel<false>,
                         cudaFuncAttributeMaxDynamicSharedMemorySize, GB_SMEM);
    cudaFuncSetAttribute(gemm_bf16s_kernel<true>,
                         cudaFuncAttributeMaxDynamicSharedMemorySize, GB_SMEM);

    // Stage: split x; transpose+split weights
    split_kernel<<<(MROWS*DMODEL/4)/256, 256>>>(x, xhi, xlo);
    transpose_split_kernel<<<dim3(DMODEL/32, DMODEL/32), 256>>>(Wq, wqh, wql);
    transpose_split_kernel<<<dim3(DMODEL/32, DMODEL/32), 256>>>(Wo, woh, wol);

    // Q projection (tensor cores, bf16 split): g_q = x * Wq
    gemm_bf16s_kernel<false><<<dim3(MROWS/128, DMODEL/128), 256, GB_SMEM>>>(
        xhi, xlo, wqh, wql, nullptr, dq);

    // K,V projections (skinny) on fp32 cores
    sgemm_kernel<64,128,16,4,8>
        <<<dim3(MROWS/64, 1), 256>>>(x, Wk, dk, MROWS, DHEAD, DMODEL);
    sgemm_kernel<64,128,16,4,8>
        <<<dim3(MROWS/64, 1), 256>>>(x, Wv, dv, MROWS, DHEAD, DMODEL);

    // Flash attention
    const int fsmem = FA_SMEM_FLOATS * (int)sizeof(float);
    cudaFuncSetAttribute(flash_kernel,
                         cudaFuncAttributeMaxDynamicSharedMemorySize, fsmem);
    flash_kernel<<<dim3(SEQ/64, NH, BATCH), 256, fsmem>>>(dq, dk, dv, da);

    // Split attn; output projection + bias on tensor cores
    split_kernel<<<(MROWS*DMODEL/4)/256, 256>>>(da, ahi, alo);
    gemm_bf16s_kernel<true><<<dim3(MROWS/128, DMODEL/128), 256, GB_SMEM>>>(
        ahi, alo, woh, wol, bo, out);
}